// round 3
// baseline (speedup 1.0000x reference)
#include <cuda_runtime.h>
#include <cuda_bf16.h>

#define T_SEQ 128
#define NBATCH 2048
#define HDIM  128
#define GDIM  384
#define XDIM  38
#define TB    16   // batch rows per CTA in recurrence kernels

// ---------------- device scratch (static allocation only) ----------------
__device__ float  g_gi[(size_t)T_SEQ * NBATCH * GDIM];    // encoder input gates (402MB)
__device__ float  g_hall[(size_t)NBATCH * T_SEQ * HDIM];  // decoder hiddens, [b][t][j] (134MB)
__device__ float  g_h0[(size_t)NBATCH * HDIM];            // encoder final state
__device__ float4 g_eWhh[32 * GDIM];   // enc_Whh transposed: [kc][g] float4 over k
__device__ float4 g_dWhh[32 * GDIM];   // dec_Whh transposed
__device__ float4 g_Wrz [32 * 256];    // dec (Whh + Wih@lin) for r,z rows, transposed
__device__ float4 g_Wcn [32 * 128];    // dec (Wih@lin) n-rows, transposed
__device__ float  g_bcomb[GDIM];       // dec_bih + dec_Wih @ lin_b
__device__ float  g_brz[256];          // g_bcomb + dec_bhh  (r,z rows)

__device__ __forceinline__ float sigf(float x) {
    return __fdividef(1.f, 1.f + __expf(-x));
}
__device__ __forceinline__ float tanhf_(float x) {
    return __fdividef(2.f, 1.f + __expf(-2.f * x)) - 1.f;
}

__device__ __forceinline__ void dot4(float& acc, const float4 hv, const float4 wv) {
    acc = fmaf(hv.x, wv.x, acc);
    acc = fmaf(hv.y, wv.y, acc);
    acc = fmaf(hv.z, wv.z, acc);
    acc = fmaf(hv.w, wv.w, acc);
}

// ---------------- weight prep: transposes, composition, biases ----------------
__global__ void prep_kernel(const float* __restrict__ eWhh, const float* __restrict__ dWhh,
                            const float* __restrict__ dWih, const float* __restrict__ linW,
                            const float* __restrict__ linb, const float* __restrict__ dbih,
                            const float* __restrict__ dbhh)
{
    int g = blockIdx.x * 128 + threadIdx.x;   // 0..383
    if (g >= GDIM) return;

    for (int kc = 0; kc < 32; ++kc) {
        const float* e = eWhh + g * HDIM + kc * 4;
        g_eWhh[kc * GDIM + g] = make_float4(e[0], e[1], e[2], e[3]);
        const float* d = dWhh + g * HDIM + kc * 4;
        g_dWhh[kc * GDIM + g] = make_float4(d[0], d[1], d[2], d[3]);
    }

    float wih[XDIM];
#pragma unroll
    for (int p = 0; p < XDIM; ++p) wih[p] = dWih[g * XDIM + p];

    float bc = dbih[g];
#pragma unroll
    for (int p = 0; p < XDIM; ++p) bc = fmaf(wih[p], linb[p], bc);
    g_bcomb[g] = bc;
    if (g < 256) g_brz[g] = bc + dbhh[g];

    // W_comb[g][k] = sum_p dec_Wih[g][p] * lin_W[p][k]
    for (int kc = 0; kc < 32; ++kc) {
        float ax = 0.f, ay = 0.f, az = 0.f, aw = 0.f;
#pragma unroll
        for (int p = 0; p < XDIM; ++p) {
            float wv = wih[p];
            const float* lp = linW + p * HDIM + kc * 4;
            ax = fmaf(wv, lp[0], ax);
            ay = fmaf(wv, lp[1], ay);
            az = fmaf(wv, lp[2], az);
            aw = fmaf(wv, lp[3], aw);
        }
        if (g < 256) {
            const float* d = dWhh + g * HDIM + kc * 4;
            g_Wrz[kc * 256 + g] = make_float4(ax + d[0], ay + d[1], az + d[2], aw + d[3]);
        } else {
            g_Wcn[kc * 128 + (g - 256)] = make_float4(ax, ay, az, aw);
        }
    }
}

// ---------------- gi_enc = x @ enc_Wih^T + enc_bih  ([T*B,38] @ [38,384]) ----------------
__global__ __launch_bounds__(384) void gi_kernel(const float* __restrict__ x,
                                                 const float* __restrict__ wih,
                                                 const float* __restrict__ bih)
{
    __shared__ float xs[32 * XDIM];
    int tid = threadIdx.x;                 // == gate index g
    int r0  = blockIdx.x * 32;             // row = b*T + t (x natural order)
    for (int i = tid; i < 32 * XDIM; i += 384) xs[i] = x[(size_t)r0 * XDIM + i];
    __syncthreads();

    float w[XDIM];
#pragma unroll
    for (int p = 0; p < XDIM; ++p) w[p] = wih[tid * XDIM + p];
    float bias = bih[tid];

    for (int b = 0; b < 32; ++b) {
        float acc = bias;
#pragma unroll
        for (int p = 0; p < XDIM; ++p) acc = fmaf(xs[b * XDIM + p], w[p], acc);
        int row = r0 + b;
        int bb  = row >> 7;        // batch index
        int tt  = row & 127;       // time index
        g_gi[((size_t)tt * NBATCH + bb) * GDIM + tid] = acc;
    }
}

// ---------------- encoder recurrence: persistent over time ----------------
__global__ __launch_bounds__(512, 1) void enc_kernel(const float* __restrict__ bhh)
{
    __shared__ float4 hs4[TB * 32];
    float* hs = (float*)hs4;
    int tid = threadIdx.x;
    int j = tid & 127, s = tid >> 7;       // j: hidden index, s: batch sub-group
    int b0 = blockIdx.x * TB;

    for (int i = tid; i < TB * HDIM; i += 512) hs[i] = 0.f;
    float bh_r = bhh[j], bh_z = bhh[j + 128], bh_n = bhh[j + 256];
    __syncthreads();

    for (int t = 0; t < T_SEQ; ++t) {
        float ar[4], az[4], an[4];
#pragma unroll
        for (int nn = 0; nn < 4; ++nn) { ar[nn] = bh_r; az[nn] = bh_z; an[nn] = bh_n; }

#pragma unroll 4
        for (int kc = 0; kc < 32; ++kc) {
            float4 wr = g_eWhh[kc * GDIM + j];
            float4 wz = g_eWhh[kc * GDIM + 128 + j];
            float4 wn = g_eWhh[kc * GDIM + 256 + j];
#pragma unroll
            for (int nn = 0; nn < 4; ++nn) {
                float4 hv = hs4[(s + nn * 4) * 32 + kc];
                dot4(ar[nn], hv, wr);
                dot4(az[nn], hv, wz);
                dot4(an[nn], hv, wn);
            }
        }

        const float* gi = g_gi + ((size_t)t * NBATCH + b0) * GDIM;
        float hn[4];
#pragma unroll
        for (int nn = 0; nn < 4; ++nn) {
            int b = s + nn * 4;
            float r = sigf(gi[b * GDIM + j] + ar[nn]);
            float z = sigf(gi[b * GDIM + 128 + j] + az[nn]);
            float n = tanhf_(gi[b * GDIM + 256 + j] + r * an[nn]);
            float h = hs[b * HDIM + j];
            hn[nn] = n + z * (h - n);
        }
        __syncthreads();
#pragma unroll
        for (int nn = 0; nn < 4; ++nn) hs[(s + nn * 4) * HDIM + j] = hn[nn];
        __syncthreads();
    }

#pragma unroll
    for (int nn = 0; nn < 4; ++nn) {
        int b = s + nn * 4;
        g_h0[(size_t)(b0 + b) * HDIM + j] = hs[b * HDIM + j];
    }
}

// ---------------- decoder recurrence (input gates composed through lin) ----------------
__global__ __launch_bounds__(512, 1) void dec_kernel(const float* __restrict__ dbih,
                                                     const float* __restrict__ dbhh)
{
    __shared__ float4 hs4[TB * 32];
    float* hs = (float*)hs4;
    int tid = threadIdx.x;
    int j = tid & 127, s = tid >> 7;
    int b0 = blockIdx.x * TB;

    for (int i = tid; i < TB * HDIM; i += 512) hs[i] = g_h0[(size_t)b0 * HDIM + i];
    float bi_r = dbih[j], bi_z = dbih[j + 128], bi_n = dbih[j + 256];
    float bh_r = dbhh[j], bh_z = dbhh[j + 128], bh_n = dbhh[j + 256];
    float brz_r = g_brz[j], brz_z = g_brz[j + 128], bcn = g_bcomb[j + 256];
    __syncthreads();

    // ---- t = 0: o_prev == 0, so gi = dec_bih; gates over plain dec_Whh ----
    {
        float ar[4], az[4], an[4];
#pragma unroll
        for (int nn = 0; nn < 4; ++nn) { ar[nn] = bh_r; az[nn] = bh_z; an[nn] = bh_n; }
#pragma unroll 4
        for (int kc = 0; kc < 32; ++kc) {
            float4 wr = g_dWhh[kc * GDIM + j];
            float4 wz = g_dWhh[kc * GDIM + 128 + j];
            float4 wn = g_dWhh[kc * GDIM + 256 + j];
#pragma unroll
            for (int nn = 0; nn < 4; ++nn) {
                float4 hv = hs4[(s + nn * 4) * 32 + kc];
                dot4(ar[nn], hv, wr);
                dot4(az[nn], hv, wz);
                dot4(an[nn], hv, wn);
            }
        }
        float hn[4];
#pragma unroll
        for (int nn = 0; nn < 4; ++nn) {
            int b = s + nn * 4;
            float r = sigf(bi_r + ar[nn]);
            float z = sigf(bi_z + az[nn]);
            float n = tanhf_(bi_n + r * an[nn]);
            float h = hs[b * HDIM + j];
            hn[nn] = n + z * (h - n);
            g_hall[((size_t)(b0 + b) * T_SEQ + 0) * HDIM + j] = hn[nn];
        }
        __syncthreads();
#pragma unroll
        for (int nn = 0; nn < 4; ++nn) hs[(s + nn * 4) * HDIM + j] = hn[nn];
        __syncthreads();
    }

    // ---- t >= 1: r,z via merged (Whh + Wcomb); n via separate Whh_n / Wcomb_n ----
    for (int t = 1; t < T_SEQ; ++t) {
        float arr[4], arz[4], ahn[4], acn[4];
#pragma unroll
        for (int nn = 0; nn < 4; ++nn) {
            arr[nn] = brz_r; arz[nn] = brz_z; ahn[nn] = bh_n; acn[nn] = bcn;
        }

#pragma unroll 4
        for (int kc = 0; kc < 32; ++kc) {
            float4 wr  = g_Wrz[kc * 256 + j];
            float4 wz  = g_Wrz[kc * 256 + 128 + j];
            float4 whn = g_dWhh[kc * GDIM + 256 + j];
            float4 wcn = g_Wcn[kc * 128 + j];
#pragma unroll
            for (int nn = 0; nn < 4; ++nn) {
                float4 hv = hs4[(s + nn * 4) * 32 + kc];
                dot4(arr[nn], hv, wr);
                dot4(arz[nn], hv, wz);
                dot4(ahn[nn], hv, whn);
                dot4(acn[nn], hv, wcn);
            }
        }

        float hn[4];
#pragma unroll
        for (int nn = 0; nn < 4; ++nn) {
            int b = s + nn * 4;
            float r = sigf(arr[nn]);
            float z = sigf(arz[nn]);
            float n = tanhf_(acn[nn] + r * ahn[nn]);
            float h = hs[b * HDIM + j];
            hn[nn] = n + z * (h - n);
            g_hall[((size_t)(b0 + b) * T_SEQ + t) * HDIM + j] = hn[nn];
        }
        __syncthreads();
#pragma unroll
        for (int nn = 0; nn < 4; ++nn) hs[(s + nn * 4) * HDIM + j] = hn[nn];
        __syncthreads();
    }
}

// ---------------- out = g_hall @ lin_W^T + lin_b  ([B*T,128] @ [128,38]) ----------------
__global__ void out_kernel(const float* __restrict__ linW, const float* __restrict__ linb,
                           float* __restrict__ out)
{
    __shared__ float hS[16 * HDIM];      // 16 rows of h
    __shared__ float lS[HDIM * XDIM];    // lin transposed: [k][p]
    int tx = threadIdx.x;   // 0..37  (output feature)
    int ty = threadIdx.y;   // 0..15  (row within block)
    int tid = ty * XDIM + tx;
    int nthr = XDIM * 16;
    size_t r0 = (size_t)blockIdx.x * 16;

    for (int i = tid; i < 16 * HDIM; i += nthr) hS[i] = g_hall[r0 * HDIM + i];
    for (int i = tid; i < HDIM * XDIM; i += nthr) {
        int k = i / XDIM, p = i - k * XDIM;
        lS[i] = linW[p * HDIM + k];
    }
    __syncthreads();

    float acc = linb[tx];
    const float* hr = hS + ty * HDIM;
#pragma unroll 8
    for (int k = 0; k < HDIM; ++k) acc = fmaf(hr[k], lS[k * XDIM + tx], acc);
    out[(r0 + ty) * XDIM + tx] = acc;
}

// ---------------- launch ----------------
extern "C" void kernel_launch(void* const* d_in, const int* in_sizes, int n_in,
                              void* d_out, int out_size) {
    const float* x        = (const float*)d_in[0];
    const float* enc_Wih  = (const float*)d_in[1];
    const float* enc_Whh  = (const float*)d_in[2];
    const float* enc_bih  = (const float*)d_in[3];
    const float* enc_bhh  = (const float*)d_in[4];
    const float* dec_Wih  = (const float*)d_in[5];
    const float* dec_Whh  = (const float*)d_in[6];
    const float* dec_bih  = (const float*)d_in[7];
    const float* dec_bhh  = (const float*)d_in[8];
    const float* lin_W    = (const float*)d_in[9];
    const float* lin_b    = (const float*)d_in[10];
    float* out = (float*)d_out;

    prep_kernel<<<3, 128>>>(enc_Whh, dec_Whh, dec_Wih, lin_W, lin_b, dec_bih, dec_bhh);
    gi_kernel<<<(T_SEQ * NBATCH) / 32, 384>>>(x, enc_Wih, enc_bih);
    enc_kernel<<<NBATCH / TB, 512>>>(enc_bhh);
    dec_kernel<<<NBATCH / TB, 512>>>(dec_bih, dec_bhh);
    out_kernel<<<(NBATCH * T_SEQ) / 16, dim3(XDIM, 16)>>>(lin_W, lin_b, out);
}

// round 4
// speedup vs baseline: 1.0113x; 1.0113x over previous
#include <cuda_runtime.h>
#include <cuda_bf16.h>

#define T_SEQ 128
#define NBATCH 2048
#define HDIM  128
#define GDIM  384
#define XDIM  38
#define TB    16   // batch rows per CTA in recurrence kernels

// ---------------- device scratch (static allocation only) ----------------
__device__ float  g_gi[(size_t)T_SEQ * NBATCH * GDIM];    // encoder input gates (402MB)
__device__ float  g_hall[(size_t)NBATCH * T_SEQ * HDIM];  // decoder hiddens, [b][t][j] (134MB)
__device__ float  g_h0[(size_t)NBATCH * HDIM];            // encoder final state
__device__ float4 g_eWhh[32 * GDIM];   // enc_Whh transposed: [kc][g] float4 over k
__device__ float4 g_dWhh[32 * GDIM];   // dec_Whh transposed
__device__ float4 g_Wrz [32 * 256];    // dec (Whh + Wih@lin) for r,z rows, transposed
__device__ float4 g_Wcn [32 * 128];    // dec (Wih@lin) n-rows, transposed
__device__ float  g_bcomb[GDIM];       // dec_bih + dec_Wih @ lin_b
__device__ float  g_brz[256];          // g_bcomb + dec_bhh  (r,z rows)

__device__ __forceinline__ float sigf(float x) {
    return __fdividef(1.f, 1.f + __expf(-x));
}
__device__ __forceinline__ float tanhf_(float x) {
    return __fdividef(2.f, 1.f + __expf(-2.f * x)) - 1.f;
}

// packed fp32x2 FMA: d += a*b elementwise on two lanes (Blackwell FFMA2)
__device__ __forceinline__ void fma2(unsigned long long& d,
                                     unsigned long long a, unsigned long long b) {
    asm("fma.rn.f32x2 %0, %1, %2, %0;" : "+l"(d) : "l"(a), "l"(b));
}
__device__ __forceinline__ float red2(unsigned long long v) {
    float lo = __uint_as_float((unsigned)(v & 0xffffffffull));
    float hi = __uint_as_float((unsigned)(v >> 32));
    return lo + hi;
}

// ---------------- weight prep: transposes, composition, biases ----------------
__global__ void prep_kernel(const float* __restrict__ eWhh, const float* __restrict__ dWhh,
                            const float* __restrict__ dWih, const float* __restrict__ linW,
                            const float* __restrict__ linb, const float* __restrict__ dbih,
                            const float* __restrict__ dbhh)
{
    int g = blockIdx.x * 128 + threadIdx.x;   // 0..383
    if (g >= GDIM) return;

    for (int kc = 0; kc < 32; ++kc) {
        const float* e = eWhh + g * HDIM + kc * 4;
        g_eWhh[kc * GDIM + g] = make_float4(e[0], e[1], e[2], e[3]);
        const float* d = dWhh + g * HDIM + kc * 4;
        g_dWhh[kc * GDIM + g] = make_float4(d[0], d[1], d[2], d[3]);
    }

    float wih[XDIM];
#pragma unroll
    for (int p = 0; p < XDIM; ++p) wih[p] = dWih[g * XDIM + p];

    float bc = dbih[g];
#pragma unroll
    for (int p = 0; p < XDIM; ++p) bc = fmaf(wih[p], linb[p], bc);
    g_bcomb[g] = bc;
    if (g < 256) g_brz[g] = bc + dbhh[g];

    // W_comb[g][k] = sum_p dec_Wih[g][p] * lin_W[p][k]
    for (int kc = 0; kc < 32; ++kc) {
        float ax = 0.f, ay = 0.f, az = 0.f, aw = 0.f;
#pragma unroll
        for (int p = 0; p < XDIM; ++p) {
            float wv = wih[p];
            const float* lp = linW + p * HDIM + kc * 4;
            ax = fmaf(wv, lp[0], ax);
            ay = fmaf(wv, lp[1], ay);
            az = fmaf(wv, lp[2], az);
            aw = fmaf(wv, lp[3], aw);
        }
        if (g < 256) {
            const float* d = dWhh + g * HDIM + kc * 4;
            g_Wrz[kc * 256 + g] = make_float4(ax + d[0], ay + d[1], az + d[2], aw + d[3]);
        } else {
            g_Wcn[kc * 128 + (g - 256)] = make_float4(ax, ay, az, aw);
        }
    }
}

// ---------------- gi_enc = x @ enc_Wih^T + enc_bih  ([T*B,38] @ [38,384]) ----------------
__global__ __launch_bounds__(384) void gi_kernel(const float* __restrict__ x,
                                                 const float* __restrict__ wih,
                                                 const float* __restrict__ bih)
{
    __shared__ float xs[32 * XDIM];
    int tid = threadIdx.x;                 // == gate index g
    int r0  = blockIdx.x * 32;             // row = b*T + t (x natural order)
    for (int i = tid; i < 32 * XDIM; i += 384) xs[i] = x[(size_t)r0 * XDIM + i];
    __syncthreads();

    float w[XDIM];
#pragma unroll
    for (int p = 0; p < XDIM; ++p) w[p] = wih[tid * XDIM + p];
    float bias = bih[tid];

    for (int b = 0; b < 32; ++b) {
        float acc = bias;
#pragma unroll
        for (int p = 0; p < XDIM; ++p) acc = fmaf(xs[b * XDIM + p], w[p], acc);
        int row = r0 + b;
        int bb  = row >> 7;        // batch index
        int tt  = row & 127;       // time index
        g_gi[((size_t)tt * NBATCH + bb) * GDIM + tid] = acc;
    }
}

// ---------------- encoder recurrence: persistent over time ----------------
__global__ __launch_bounds__(512, 1) void enc_kernel(const float* __restrict__ bhh)
{
    __shared__ float4 hs4[2][TB * 32];            // double-buffered h
    int tid = threadIdx.x;
    int j = tid & 127, s = tid >> 7;              // j: hidden index, s: batch sub-group
    int b0 = blockIdx.x * TB;

    float* hs0 = (float*)hs4[0];
    for (int i = tid; i < TB * HDIM; i += 512) hs0[i] = 0.f;
    float bh_r = bhh[j], bh_z = bhh[j + 128], bh_n = bhh[j + 256];
    __syncthreads();

    for (int t = 0; t < T_SEQ; ++t) {
        int cur = t & 1, nxt = cur ^ 1;
        const ulonglong2* hbuf = (const ulonglong2*)hs4[cur];
        float* hw = (float*)hs4[nxt];
        const float* hr = (const float*)hs4[cur];

        unsigned long long ar2[4], az2[4], an2[4];
#pragma unroll
        for (int nn = 0; nn < 4; ++nn) { ar2[nn] = 0ull; az2[nn] = 0ull; an2[nn] = 0ull; }

#pragma unroll 4
        for (int kc = 0; kc < 32; ++kc) {
            ulonglong2 wr = *(const ulonglong2*)&g_eWhh[kc * GDIM + j];
            ulonglong2 wz = *(const ulonglong2*)&g_eWhh[kc * GDIM + 128 + j];
            ulonglong2 wn = *(const ulonglong2*)&g_eWhh[kc * GDIM + 256 + j];
#pragma unroll
            for (int nn = 0; nn < 4; ++nn) {
                ulonglong2 hv = hbuf[(s + nn * 4) * 32 + kc];
                fma2(ar2[nn], hv.x, wr.x); fma2(ar2[nn], hv.y, wr.y);
                fma2(az2[nn], hv.x, wz.x); fma2(az2[nn], hv.y, wz.y);
                fma2(an2[nn], hv.x, wn.x); fma2(an2[nn], hv.y, wn.y);
            }
        }

        const float* gi = g_gi + ((size_t)t * NBATCH + b0) * GDIM;
#pragma unroll
        for (int nn = 0; nn < 4; ++nn) {
            int b = s + nn * 4;
            float r = sigf(gi[b * GDIM + j] + bh_r + red2(ar2[nn]));
            float z = sigf(gi[b * GDIM + 128 + j] + bh_z + red2(az2[nn]));
            float n = tanhf_(gi[b * GDIM + 256 + j] + bh_n + r * (bh_n * 0.f + red2(an2[nn]) + bh_n - bh_n));
            // (simplify) n uses bh_n inside r-scaled term:
            n = tanhf_(gi[b * GDIM + 256 + j] + r * (red2(an2[nn]) + bh_n));
            float h = hr[b * HDIM + j];
            hw[b * HDIM + j] = n + z * (h - n);
        }
        __syncthreads();
    }

    const float* hf = (const float*)hs4[T_SEQ & 1];
#pragma unroll
    for (int nn = 0; nn < 4; ++nn) {
        int b = s + nn * 4;
        g_h0[(size_t)(b0 + b) * HDIM + j] = hf[b * HDIM + j];
    }
}

// ---------------- decoder recurrence (input gates composed through lin) ----------------
__global__ __launch_bounds__(512, 1) void dec_kernel(const float* __restrict__ dbih,
                                                     const float* __restrict__ dbhh)
{
    __shared__ float4 hs4[2][TB * 32];
    int tid = threadIdx.x;
    int j = tid & 127, s = tid >> 7;
    int b0 = blockIdx.x * TB;

    float* hs0 = (float*)hs4[0];
    for (int i = tid; i < TB * HDIM; i += 512) hs0[i] = g_h0[(size_t)b0 * HDIM + i];
    float bi_r = dbih[j], bi_z = dbih[j + 128], bi_n = dbih[j + 256];
    float bh_r = dbhh[j], bh_z = dbhh[j + 128], bh_n = dbhh[j + 256];
    float brz_r = g_brz[j], brz_z = g_brz[j + 128], bcn = g_bcomb[j + 256];
    __syncthreads();

    // ---- t = 0: o_prev == 0, so gi = dec_bih; gates over plain dec_Whh ----
    {
        const ulonglong2* hbuf = (const ulonglong2*)hs4[0];
        const float* hr = (const float*)hs4[0];
        float* hw = (float*)hs4[1];

        unsigned long long ar2[4], az2[4], an2[4];
#pragma unroll
        for (int nn = 0; nn < 4; ++nn) { ar2[nn] = 0ull; az2[nn] = 0ull; an2[nn] = 0ull; }
#pragma unroll 4
        for (int kc = 0; kc < 32; ++kc) {
            ulonglong2 wr = *(const ulonglong2*)&g_dWhh[kc * GDIM + j];
            ulonglong2 wz = *(const ulonglong2*)&g_dWhh[kc * GDIM + 128 + j];
            ulonglong2 wn = *(const ulonglong2*)&g_dWhh[kc * GDIM + 256 + j];
#pragma unroll
            for (int nn = 0; nn < 4; ++nn) {
                ulonglong2 hv = hbuf[(s + nn * 4) * 32 + kc];
                fma2(ar2[nn], hv.x, wr.x); fma2(ar2[nn], hv.y, wr.y);
                fma2(az2[nn], hv.x, wz.x); fma2(az2[nn], hv.y, wz.y);
                fma2(an2[nn], hv.x, wn.x); fma2(an2[nn], hv.y, wn.y);
            }
        }
#pragma unroll
        for (int nn = 0; nn < 4; ++nn) {
            int b = s + nn * 4;
            float r = sigf(bi_r + bh_r + red2(ar2[nn]));
            float z = sigf(bi_z + bh_z + red2(az2[nn]));
            float n = tanhf_(bi_n + r * (red2(an2[nn]) + bh_n));
            float h = hr[b * HDIM + j];
            float hnv = n + z * (h - n);
            hw[b * HDIM + j] = hnv;
            g_hall[((size_t)(b0 + b) * T_SEQ + 0) * HDIM + j] = hnv;
        }
        __syncthreads();
    }

    // ---- t >= 1: r,z via merged (Whh + Wcomb); n via separate Whh_n / Wcomb_n ----
    for (int t = 1; t < T_SEQ; ++t) {
        int cur = t & 1, nxt = cur ^ 1;
        const ulonglong2* hbuf = (const ulonglong2*)hs4[cur];
        const float* hr = (const float*)hs4[cur];
        float* hw = (float*)hs4[nxt];

        unsigned long long arr2[4], arz2[4], ahn2[4], acn2[4];
#pragma unroll
        for (int nn = 0; nn < 4; ++nn) {
            arr2[nn] = 0ull; arz2[nn] = 0ull; ahn2[nn] = 0ull; acn2[nn] = 0ull;
        }

#pragma unroll 4
        for (int kc = 0; kc < 32; ++kc) {
            ulonglong2 wr  = *(const ulonglong2*)&g_Wrz[kc * 256 + j];
            ulonglong2 wz  = *(const ulonglong2*)&g_Wrz[kc * 256 + 128 + j];
            ulonglong2 whn = *(const ulonglong2*)&g_dWhh[kc * GDIM + 256 + j];
            ulonglong2 wcn = *(const ulonglong2*)&g_Wcn[kc * 128 + j];
#pragma unroll
            for (int nn = 0; nn < 4; ++nn) {
                ulonglong2 hv = hbuf[(s + nn * 4) * 32 + kc];
                fma2(arr2[nn], hv.x, wr.x);  fma2(arr2[nn], hv.y, wr.y);
                fma2(arz2[nn], hv.x, wz.x);  fma2(arz2[nn], hv.y, wz.y);
                fma2(ahn2[nn], hv.x, whn.x); fma2(ahn2[nn], hv.y, whn.y);
                fma2(acn2[nn], hv.x, wcn.x); fma2(acn2[nn], hv.y, wcn.y);
            }
        }

#pragma unroll
        for (int nn = 0; nn < 4; ++nn) {
            int b = s + nn * 4;
            float r = sigf(brz_r + red2(arr2[nn]));
            float z = sigf(brz_z + red2(arz2[nn]));
            float n = tanhf_(bcn + red2(acn2[nn]) + r * (red2(ahn2[nn]) + bh_n));
            float h = hr[b * HDIM + j];
            float hnv = n + z * (h - n);
            hw[b * HDIM + j] = hnv;
            g_hall[((size_t)(b0 + b) * T_SEQ + t) * HDIM + j] = hnv;
        }
        __syncthreads();
    }
}

// ---------------- out = g_hall @ lin_W^T + lin_b  ([B*T,128] @ [128,38]) ----------------
__global__ void out_kernel(const float* __restrict__ linW, const float* __restrict__ linb,
                           float* __restrict__ out)
{
    __shared__ float hS[16 * HDIM];      // 16 rows of h
    __shared__ float lS[HDIM * XDIM];    // lin transposed: [k][p]
    int tx = threadIdx.x;   // 0..37  (output feature)
    int ty = threadIdx.y;   // 0..15  (row within block)
    int tid = ty * XDIM + tx;
    int nthr = XDIM * 16;
    size_t r0 = (size_t)blockIdx.x * 16;

    for (int i = tid; i < 16 * HDIM; i += nthr) hS[i] = g_hall[r0 * HDIM + i];
    for (int i = tid; i < HDIM * XDIM; i += nthr) {
        int k = i / XDIM, p = i - k * XDIM;
        lS[i] = linW[p * HDIM + k];
    }
    __syncthreads();

    float acc = linb[tx];
    const float* hrow = hS + ty * HDIM;
#pragma unroll 8
    for (int k = 0; k < HDIM; ++k) acc = fmaf(hrow[k], lS[k * XDIM + tx], acc);
    out[(r0 + ty) * XDIM + tx] = acc;
}

// ---------------- launch ----------------
extern "C" void kernel_launch(void* const* d_in, const int* in_sizes, int n_in,
                              void* d_out, int out_size) {
    const float* x        = (const float*)d_in[0];
    const float* enc_Wih  = (const float*)d_in[1];
    const float* enc_Whh  = (const float*)d_in[2];
    const float* enc_bih  = (const float*)d_in[3];
    const float* enc_bhh  = (const float*)d_in[4];
    const float* dec_Wih  = (const float*)d_in[5];
    const float* dec_Whh  = (const float*)d_in[6];
    const float* dec_bih  = (const float*)d_in[7];
    const float* dec_bhh  = (const float*)d_in[8];
    const float* lin_W    = (const float*)d_in[9];
    const float* lin_b    = (const float*)d_in[10];
    float* out = (float*)d_out;

    prep_kernel<<<3, 128>>>(enc_Whh, dec_Whh, dec_Wih, lin_W, lin_b, dec_bih, dec_bhh);
    gi_kernel<<<(T_SEQ * NBATCH) / 32, 384>>>(x, enc_Wih, enc_bih);
    enc_kernel<<<NBATCH / TB, 512>>>(enc_bhh);
    dec_kernel<<<NBATCH / TB, 512>>>(dec_bih, dec_bhh);
    out_kernel<<<(NBATCH * T_SEQ) / 16, dim3(XDIM, 16)>>>(lin_W, lin_b, out);
}

// round 6
// speedup vs baseline: 1.7339x; 1.7144x over previous
#include <cuda_runtime.h>
#include <cuda_bf16.h>
#include <cstdint>

#define T_SEQ 128
#define NBATCH 2048
#define HDIM  128
#define GDIM  384
#define XDIM  38
#define TB    16

// ---------------- device scratch ----------------
__device__ float  g_gi[(size_t)T_SEQ * NBATCH * GDIM];
__device__ float  g_hall[(size_t)NBATCH * T_SEQ * HDIM];  // [b][t][j]
__device__ float  g_h0[(size_t)NBATCH * HDIM];
__device__ float  g_h1[(size_t)NBATCH * HDIM];
__device__ float4 g_dWhh4[32 * GDIM];
__device__ float  g_Wrz_rm[256 * HDIM];
__device__ float  g_Wcn_rm[128 * HDIM];
__device__ float  g_bcomb[GDIM];
__device__ float  g_brz[256];

__device__ __forceinline__ float sigf(float x)  { return __fdividef(1.f, 1.f + __expf(-x)); }
__device__ __forceinline__ float tanhf_(float x){ return __fdividef(2.f, 1.f + __expf(-2.f * x)) - 1.f; }

__device__ __forceinline__ uint32_t smem_u32(const void* p) {
    uint32_t a;
    asm("{ .reg .u64 t; cvta.to.shared.u64 t, %1; cvt.u32.u64 %0, t; }" : "=r"(a) : "l"(p));
    return a;
}

#define LDSM4(r, a) \
    asm volatile("ldmatrix.sync.aligned.m8n8.x4.shared.b16 {%0,%1,%2,%3}, [%4];" \
        : "=r"((r)[0]), "=r"((r)[1]), "=r"((r)[2]), "=r"((r)[3]) : "r"(a))

#define MMA16816(d, a, b0, b1) \
    asm volatile("mma.sync.aligned.m16n8k16.row.col.f32.bf16.bf16.f32 " \
        "{%0,%1,%2,%3}, {%4,%5,%6,%7}, {%8,%9}, {%0,%1,%2,%3};" \
        : "+f"((d)[0]), "+f"((d)[1]), "+f"((d)[2]), "+f"((d)[3]) \
        : "r"((a)[0]), "r"((a)[1]), "r"((a)[2]), "r"((a)[3]), "r"(b0), "r"(b1))

// smem strides (bytes): bf16 tiles padded to 272B rows (conflict-free ldmatrix), G padded 17 floats
#define WSTR 272
#define GSTR 17

// dec smem map
#define D_WSM 0
#define D_G   139264            // 512*272
#define D_H   174080            // + 512*17*4
#define D_HHI 182272            // + 2048*4
#define D_HLO 186624            // + 16*272
#define D_SZ  190976
// enc smem map
#define E_WSM 0
#define E_G   104448            // 384*272
#define E_H   130560            // + 384*17*4
#define E_HHI 138752
#define E_HLO 143104
#define E_SZ  147456

// ---------------- weight prep ----------------
__global__ void prep_kernel(const float* __restrict__ dWhh,
                            const float* __restrict__ dWih, const float* __restrict__ linW,
                            const float* __restrict__ linb, const float* __restrict__ dbih,
                            const float* __restrict__ dbhh)
{
    int g = blockIdx.x * 128 + threadIdx.x;
    if (g >= GDIM) return;

    for (int kc = 0; kc < 32; ++kc) {
        const float* d = dWhh + g * HDIM + kc * 4;
        g_dWhh4[kc * GDIM + g] = make_float4(d[0], d[1], d[2], d[3]);
    }

    float wih[XDIM];
#pragma unroll
    for (int p = 0; p < XDIM; ++p) wih[p] = dWih[g * XDIM + p];

    float bc = dbih[g];
#pragma unroll
    for (int p = 0; p < XDIM; ++p) bc = fmaf(wih[p], linb[p], bc);
    g_bcomb[g] = bc;
    if (g < 256) g_brz[g] = bc + dbhh[g];

    for (int kc = 0; kc < 32; ++kc) {
        float a4[4] = {0.f, 0.f, 0.f, 0.f};
#pragma unroll
        for (int p = 0; p < XDIM; ++p) {
            float wv = wih[p];
            const float* lp = linW + p * HDIM + kc * 4;
            a4[0] = fmaf(wv, lp[0], a4[0]);
            a4[1] = fmaf(wv, lp[1], a4[1]);
            a4[2] = fmaf(wv, lp[2], a4[2]);
            a4[3] = fmaf(wv, lp[3], a4[3]);
        }
        if (g < 256) {
            const float* d = dWhh + g * HDIM + kc * 4;
#pragma unroll
            for (int n = 0; n < 4; ++n) g_Wrz_rm[g * HDIM + kc * 4 + n] = a4[n] + d[n];
        } else {
#pragma unroll
            for (int n = 0; n < 4; ++n) g_Wcn_rm[(g - 256) * HDIM + kc * 4 + n] = a4[n];
        }
    }
}

// ---------------- gi = x @ enc_Wih^T + enc_bih ----------------
__global__ __launch_bounds__(384) void gi_kernel(const float* __restrict__ x,
                                                 const float* __restrict__ wih,
                                                 const float* __restrict__ bih)
{
    __shared__ float xs[32 * XDIM];
    int tid = threadIdx.x;
    int r0  = blockIdx.x * 32;
    for (int i = tid; i < 32 * XDIM; i += 384) xs[i] = x[(size_t)r0 * XDIM + i];
    __syncthreads();

    float w[XDIM];
#pragma unroll
    for (int p = 0; p < XDIM; ++p) w[p] = wih[tid * XDIM + p];
    float bias = bih[tid];

    for (int b = 0; b < 32; ++b) {
        float acc = bias;
#pragma unroll
        for (int p = 0; p < XDIM; ++p) acc = fmaf(xs[b * XDIM + p], w[p], acc);
        int row = r0 + b;
        g_gi[((size_t)(row & 127) * NBATCH + (row >> 7)) * GDIM + tid] = acc;
    }
}

// stage helpers: write bf16 hi or lo of W row-major into Wsm (stride 272B)
__device__ __forceinline__ void stage_w(char* smem, const float* src, int row, int k, bool lo) {
    float w = src[k];
    __nv_bfloat16 hb = __float2bfloat16_rn(w);
    __nv_bfloat16 v = lo ? __float2bfloat16_rn(w - __bfloat162float(hb)) : hb;
    *(__nv_bfloat16*)(smem + row * WSTR + k * 2) = v;
}

// ---------------- encoder recurrence (warp mma) ----------------
__global__ __launch_bounds__(512, 1) void enc_tc_kernel(const float* __restrict__ eWhh,
                                                        const float* __restrict__ bhh)
{
    extern __shared__ char smem[];
    uint32_t sb = smem_u32(smem);
    int tid = threadIdx.x, wid = tid >> 5, lane = tid & 31;
    int b0 = blockIdx.x * TB;
    float* Gf  = (float*)(smem + E_G);
    float* hsm = (float*)(smem + E_H);

    // stage W_hi
    for (int i = tid; i < GDIM * HDIM; i += 512)
        stage_w(smem + E_WSM, eWhh + (i >> 7) * HDIM, i >> 7, i & 127, false);
    __syncthreads();

    // resident W_hi fragments (warps 0-11)
    uint32_t whi[2][8][4];
    uint32_t baseA = sb + E_WSM + (wid * 32 + (lane & 15)) * WSTR + (lane >> 4) * 16;
    if (wid < 12) {
#pragma unroll
        for (int m = 0; m < 2; ++m)
#pragma unroll
            for (int kc = 0; kc < 8; ++kc)
                LDSM4(whi[m][kc], baseA + m * 16 * WSTR + kc * 32);
    }
    __syncthreads();

    // stage W_lo, zero h buffers
    for (int i = tid; i < GDIM * HDIM; i += 512)
        stage_w(smem + E_WSM, eWhh + (i >> 7) * HDIM, i >> 7, i & 127, true);
    for (int i = tid; i < TB * HDIM; i += 512) {
        hsm[i] = 0.f;
        int c = i >> 7, j = i & 127;
        *(__nv_bfloat16*)(smem + E_HHI + c * WSTR + j * 2) = __float2bfloat16_rn(0.f);
        *(__nv_bfloat16*)(smem + E_HLO + c * WSTR + j * 2) = __float2bfloat16_rn(0.f);
    }

    float bh_r = bhh[tid & 127], bh_z = bhh[(tid & 127) + 128], bh_n = bhh[(tid & 127) + 256];
    uint32_t baseBh = sb + E_HHI + (lane & 7) * WSTR + (lane >> 3) * 16;
    uint32_t baseBl = sb + E_HLO + (lane & 7) * WSTR + (lane >> 3) * 16;
    int gq = lane >> 2, tig = lane & 3;
    int jj = tid & 127, c0 = tid >> 7;
    __syncthreads();

    for (int t = 0; t < T_SEQ; ++t) {
        // prefetch gi for this step (hidden under mma)
        float gir[4], giz[4], gin[4];
        const float* gp = g_gi + ((size_t)t * NBATCH + b0) * GDIM;
#pragma unroll
        for (int i = 0; i < 4; ++i) {
            int c = c0 + i * 4;
            gir[i] = gp[c * GDIM + jj];
            giz[i] = gp[c * GDIM + 128 + jj];
            gin[i] = gp[c * GDIM + 256 + jj];
        }

        if (wid < 12) {
            float d[2][2][4];
#pragma unroll
            for (int m = 0; m < 2; ++m)
#pragma unroll
                for (int n = 0; n < 2; ++n)
#pragma unroll
                    for (int q = 0; q < 4; ++q) d[m][n][q] = 0.f;

#pragma unroll
            for (int kp = 0; kp < 4; ++kp) {
                uint32_t bh[2][4], bl[2][4];
                LDSM4(bh[0], baseBh + kp * 64);
                LDSM4(bh[1], baseBh + 8 * WSTR + kp * 64);
                LDSM4(bl[0], baseBl + kp * 64);
                LDSM4(bl[1], baseBl + 8 * WSTR + kp * 64);
#pragma unroll
                for (int ch = 0; ch < 2; ++ch) {
                    int kc = kp * 2 + ch;
                    uint32_t al[2][4];
                    LDSM4(al[0], baseA + kc * 32);
                    LDSM4(al[1], baseA + 16 * WSTR + kc * 32);
#pragma unroll
                    for (int m = 0; m < 2; ++m)
#pragma unroll
                        for (int n = 0; n < 2; ++n) {
                            MMA16816(d[m][n], whi[m][kc], bh[n][2 * ch], bh[n][2 * ch + 1]);
                            MMA16816(d[m][n], whi[m][kc], bl[n][2 * ch], bl[n][2 * ch + 1]);
                            MMA16816(d[m][n], al[m],      bh[n][2 * ch], bh[n][2 * ch + 1]);
                        }
                }
            }
            // write gates to G
#pragma unroll
            for (int m = 0; m < 2; ++m)
#pragma unroll
                for (int n = 0; n < 2; ++n) {
                    int row = wid * 32 + m * 16 + gq;
                    int col = n * 8 + 2 * tig;
                    Gf[row * GSTR + col]           = d[m][n][0];
                    Gf[row * GSTR + col + 1]       = d[m][n][1];
                    Gf[(row + 8) * GSTR + col]     = d[m][n][2];
                    Gf[(row + 8) * GSTR + col + 1] = d[m][n][3];
                }
        }
        __syncthreads();

        // epilogue: all 512 threads, 4 (j,c) each
#pragma unroll
        for (int i = 0; i < 4; ++i) {
            int c = c0 + i * 4;
            float r = sigf(gir[i] + bh_r + Gf[jj * GSTR + c]);
            float z = sigf(giz[i] + bh_z + Gf[(128 + jj) * GSTR + c]);
            float n = tanhf_(gin[i] + r * (Gf[(256 + jj) * GSTR + c] + bh_n));
            float h = hsm[c * HDIM + jj];
            float hv = n + z * (h - n);
            hsm[c * HDIM + jj] = hv;
            __nv_bfloat16 hb = __float2bfloat16_rn(hv);
            *(__nv_bfloat16*)(smem + E_HHI + c * WSTR + jj * 2) = hb;
            *(__nv_bfloat16*)(smem + E_HLO + c * WSTR + jj * 2) =
                __float2bfloat16_rn(hv - __bfloat162float(hb));
        }
        __syncthreads();
    }

#pragma unroll
    for (int i = 0; i < 4; ++i) {
        int c = c0 + i * 4;
        g_h0[(size_t)(b0 + c) * HDIM + jj] = hsm[c * HDIM + jj];
    }
}

// ---------------- decoder t=0 (plain FFMA) ----------------
__global__ __launch_bounds__(512, 1) void dec0_kernel(const float* __restrict__ dbih,
                                                      const float* __restrict__ dbhh)
{
    __shared__ float4 hs4[TB * 32];
    float* hs = (float*)hs4;
    int tid = threadIdx.x;
    int j = tid & 127, s = tid >> 7;
    int b0 = blockIdx.x * TB;

    for (int i = tid; i < TB * HDIM; i += 512) hs[i] = g_h0[(size_t)b0 * HDIM + i];
    float bi_r = dbih[j], bi_z = dbih[j + 128], bi_n = dbih[j + 256];
    __syncthreads();

    float ar[4] = {0, 0, 0, 0}, az[4] = {0, 0, 0, 0}, an[4] = {0, 0, 0, 0};
#pragma unroll 4
    for (int kc = 0; kc < 32; ++kc) {
        float4 wr = g_dWhh4[kc * GDIM + j];
        float4 wz = g_dWhh4[kc * GDIM + 128 + j];
        float4 wn = g_dWhh4[kc * GDIM + 256 + j];
#pragma unroll
        for (int nn = 0; nn < 4; ++nn) {
            float4 hv = hs4[(s + nn * 4) * 32 + kc];
            ar[nn] = fmaf(hv.x, wr.x, ar[nn]); ar[nn] = fmaf(hv.y, wr.y, ar[nn]);
            ar[nn] = fmaf(hv.z, wr.z, ar[nn]); ar[nn] = fmaf(hv.w, wr.w, ar[nn]);
            az[nn] = fmaf(hv.x, wz.x, az[nn]); az[nn] = fmaf(hv.y, wz.y, az[nn]);
            az[nn] = fmaf(hv.z, wz.z, az[nn]); az[nn] = fmaf(hv.w, wz.w, az[nn]);
            an[nn] = fmaf(hv.x, wn.x, an[nn]); an[nn] = fmaf(hv.y, wn.y, an[nn]);
            an[nn] = fmaf(hv.z, wn.z, an[nn]); an[nn] = fmaf(hv.w, wn.w, an[nn]);
        }
    }
    float bh_r = dbhh[j], bh_z = dbhh[j + 128], bh_n = dbhh[j + 256];
#pragma unroll
    for (int nn = 0; nn < 4; ++nn) {
        int b = s + nn * 4;
        float r = sigf(bi_r + bh_r + ar[nn]);
        float z = sigf(bi_z + bh_z + az[nn]);
        float n = tanhf_(bi_n + r * (an[nn] + bh_n));
        float h = hs[b * HDIM + j];
        float hv = n + z * (h - n);
        g_hall[((size_t)(b0 + b) * T_SEQ + 0) * HDIM + j] = hv;
        g_h1[(size_t)(b0 + b) * HDIM + j] = hv;
    }
}

// ---------------- decoder recurrence t=1..127 (warp mma) ----------------
__global__ __launch_bounds__(512, 1) void dec_tc_kernel(const float* __restrict__ dWhh,
                                                        const float* __restrict__ dbhh)
{
    extern __shared__ char smem[];
    uint32_t sb = smem_u32(smem);
    int tid = threadIdx.x, wid = tid >> 5, lane = tid & 31;
    int b0 = blockIdx.x * TB;
    float* Gf  = (float*)(smem + D_G);
    float* hsm = (float*)(smem + D_H);

    // stage W_hi: rows 0-255 Wrz, 256-383 dWhh(n), 384-511 Wcn
    for (int i = tid; i < 512 * HDIM; i += 512) {
        int row = i >> 7, k = i & 127;
        const float* src = (row < 256) ? (g_Wrz_rm + row * HDIM)
                        : (row < 384) ? (dWhh + row * HDIM)
                                      : (g_Wcn_rm + (row - 384) * HDIM);
        stage_w(smem + D_WSM, src, row, k, false);
    }
    __syncthreads();

    uint32_t whi[2][8][4];
    uint32_t baseA = sb + D_WSM + (wid * 32 + (lane & 15)) * WSTR + (lane >> 4) * 16;
#pragma unroll
    for (int m = 0; m < 2; ++m)
#pragma unroll
        for (int kc = 0; kc < 8; ++kc)
            LDSM4(whi[m][kc], baseA + m * 16 * WSTR + kc * 32);
    __syncthreads();

    // stage W_lo + h1
    for (int i = tid; i < 512 * HDIM; i += 512) {
        int row = i >> 7, k = i & 127;
        const float* src = (row < 256) ? (g_Wrz_rm + row * HDIM)
                        : (row < 384) ? (dWhh + row * HDIM)
                                      : (g_Wcn_rm + (row - 384) * HDIM);
        stage_w(smem + D_WSM, src, row, k, true);
    }
    for (int i = tid; i < TB * HDIM; i += 512) {
        int c = i >> 7, j = i & 127;
        float hv = g_h1[(size_t)(b0 + c) * HDIM + j];
        hsm[i] = hv;
        __nv_bfloat16 hb = __float2bfloat16_rn(hv);
        *(__nv_bfloat16*)(smem + D_HHI + c * WSTR + j * 2) = hb;
        *(__nv_bfloat16*)(smem + D_HLO + c * WSTR + j * 2) =
            __float2bfloat16_rn(hv - __bfloat162float(hb));
    }

    int jj = tid & 127, c0 = tid >> 7;
    float brz_r = g_brz[jj], brz_z = g_brz[jj + 128];
    float bcn = g_bcomb[jj + 256], bh_n = dbhh[jj + 256];
    uint32_t baseBh = sb + D_HHI + (lane & 7) * WSTR + (lane >> 3) * 16;
    uint32_t baseBl = sb + D_HLO + (lane & 7) * WSTR + (lane >> 3) * 16;
    int gq = lane >> 2, tig = lane & 3;
    __syncthreads();

    for (int tt = 0; tt < T_SEQ - 1; ++tt) {
        float d[2][2][4];
#pragma unroll
        for (int m = 0; m < 2; ++m)
#pragma unroll
            for (int n = 0; n < 2; ++n)
#pragma unroll
                for (int q = 0; q < 4; ++q) d[m][n][q] = 0.f;

#pragma unroll
        for (int kp = 0; kp < 4; ++kp) {
            uint32_t bh[2][4], bl[2][4];
            LDSM4(bh[0], baseBh + kp * 64);
            LDSM4(bh[1], baseBh + 8 * WSTR + kp * 64);
            LDSM4(bl[0], baseBl + kp * 64);
            LDSM4(bl[1], baseBl + 8 * WSTR + kp * 64);
#pragma unroll
            for (int ch = 0; ch < 2; ++ch) {
                int kc = kp * 2 + ch;
                uint32_t al[2][4];
                LDSM4(al[0], baseA + kc * 32);
                LDSM4(al[1], baseA + 16 * WSTR + kc * 32);
#pragma unroll
                for (int m = 0; m < 2; ++m)
#pragma unroll
                    for (int n = 0; n < 2; ++n) {
                        MMA16816(d[m][n], whi[m][kc], bh[n][2 * ch], bh[n][2 * ch + 1]);
                        MMA16816(d[m][n], whi[m][kc], bl[n][2 * ch], bl[n][2 * ch + 1]);
                        MMA16816(d[m][n], al[m],      bh[n][2 * ch], bh[n][2 * ch + 1]);
                    }
            }
        }
#pragma unroll
        for (int m = 0; m < 2; ++m)
#pragma unroll
            for (int n = 0; n < 2; ++n) {
                int row = wid * 32 + m * 16 + gq;
                int col = n * 8 + 2 * tig;
                Gf[row * GSTR + col]           = d[m][n][0];
                Gf[row * GSTR + col + 1]       = d[m][n][1];
                Gf[(row + 8) * GSTR + col]     = d[m][n][2];
                Gf[(row + 8) * GSTR + col + 1] = d[m][n][3];
            }
        __syncthreads();

#pragma unroll
        for (int i = 0; i < 4; ++i) {
            int c = c0 + i * 4;
            float r = sigf(brz_r + Gf[jj * GSTR + c]);
            float z = sigf(brz_z + Gf[(128 + jj) * GSTR + c]);
            float n = tanhf_(bcn + Gf[(384 + jj) * GSTR + c]
                             + r * (Gf[(256 + jj) * GSTR + c] + bh_n));
            float h = hsm[c * HDIM + jj];
            float hv = n + z * (h - n);
            hsm[c * HDIM + jj] = hv;
            g_hall[((size_t)(b0 + c) * T_SEQ + tt + 1) * HDIM + jj] = hv;
            __nv_bfloat16 hb = __float2bfloat16_rn(hv);
            *(__nv_bfloat16*)(smem + D_HHI + c * WSTR + jj * 2) = hb;
            *(__nv_bfloat16*)(smem + D_HLO + c * WSTR + jj * 2) =
                __float2bfloat16_rn(hv - __bfloat162float(hb));
        }
        __syncthreads();
    }
}

// ---------------- out = g_hall @ lin_W^T + lin_b ----------------
__global__ void out_kernel(const float* __restrict__ linW, const float* __restrict__ linb,
                           float* __restrict__ out)
{
    __shared__ float hS[16 * HDIM];
    __shared__ float lS[HDIM * XDIM];
    int tx = threadIdx.x, ty = threadIdx.y;
    int tid = ty * XDIM + tx;
    int nthr = XDIM * 16;
    size_t r0 = (size_t)blockIdx.x * 16;

    for (int i = tid; i < 16 * HDIM; i += nthr) hS[i] = g_hall[r0 * HDIM + i];
    for (int i = tid; i < HDIM * XDIM; i += nthr) {
        int k = i / XDIM, p = i - k * XDIM;
        lS[i] = linW[p * HDIM + k];
    }
    __syncthreads();

    float acc = linb[tx];
    const float* hrow = hS + ty * HDIM;
#pragma unroll 8
    for (int k = 0; k < HDIM; ++k) acc = fmaf(hrow[k], lS[k * XDIM + tx], acc);
    out[(r0 + ty) * XDIM + tx] = acc;
}

// ---------------- launch ----------------
extern "C" void kernel_launch(void* const* d_in, const int* in_sizes, int n_in,
                              void* d_out, int out_size) {
    const float* x        = (const float*)d_in[0];
    const float* enc_Wih  = (const float*)d_in[1];
    const float* enc_Whh  = (const float*)d_in[2];
    const float* enc_bih  = (const float*)d_in[3];
    const float* enc_bhh  = (const float*)d_in[4];
    const float* dec_Wih  = (const float*)d_in[5];
    const float* dec_Whh  = (const float*)d_in[6];
    const float* dec_bih  = (const float*)d_in[7];
    const float* dec_bhh  = (const float*)d_in[8];
    const float* lin_W    = (const float*)d_in[9];
    const float* lin_b    = (const float*)d_in[10];
    float* out = (float*)d_out;

    cudaFuncSetAttribute(enc_tc_kernel, cudaFuncAttributeMaxDynamicSharedMemorySize, E_SZ);
    cudaFuncSetAttribute(dec_tc_kernel, cudaFuncAttributeMaxDynamicSharedMemorySize, D_SZ);

    prep_kernel<<<3, 128>>>(dec_Whh, dec_Wih, lin_W, lin_b, dec_bih, dec_bhh);
    gi_kernel<<<(T_SEQ * NBATCH) / 32, 384>>>(x, enc_Wih, enc_bih);
    enc_tc_kernel<<<NBATCH / TB, 512, E_SZ>>>(enc_Whh, enc_bhh);
    dec0_kernel<<<NBATCH / TB, 512>>>(dec_bih, dec_bhh);
    dec_tc_kernel<<<NBATCH / TB, 512, D_SZ>>>(dec_Whh, dec_bhh);
    out_kernel<<<(NBATCH * T_SEQ) / 16, dim3(XDIM, 16)>>>(lin_W, lin_b, out);
}